// round 11
// baseline (speedup 1.0000x reference)
#include <cuda_runtime.h>
#include <cuda_bf16.h>
#include <cstdint>

#define ALPHA 0.2f
#define KDIM 4096
#define NDIM 1024
#define CH 16
#define NCHUNK (KDIM / CH)   // 256
#define NBLK 256

// ---------------- scratch (__device__ globals; no allocs allowed) ----------
__device__ float g_s1[KDIM], g_s2[KDIM];
__device__ float g_ea[KDIM], g_ec[KDIM];        // exp(s1), exp(0.2 s1)
__device__ float g_eb[KDIM], g_ed[KDIM];        // exp(s2), exp(0.2 s2)
__device__ float g_sorted[KDIM];                // s2 ascending
__device__ int   g_sigma[KDIM];                 // sorted rank -> original index
__device__ float g_ebS[KDIM], g_edS[KDIM];      // eb/ed in sorted order
__device__ float g_sb[KDIM + 1], g_sd[KDIM + 1];// scalar global suffix sums
__device__ float g_sufB[(size_t)KDIM * NDIM];   // chunk-local vector suffix sums
__device__ float g_sufD[(size_t)KDIM * NDIM];
__device__ float g_carB[NCHUNK * NDIM];         // exclusive chunk-suffix carries
__device__ float g_carD[NCHUNK * NDIM];
// grid barrier state (barcnt returns to 0 after every use -> graph-replay safe)
__device__ unsigned int g_barcnt;
__device__ volatile unsigned int g_bargen;

// ---------------------------------------------------------------------------
__device__ __forceinline__ void gsync(unsigned int& gen) {
    __syncthreads();
    if (threadIdx.x == 0) {
        __threadfence();
        unsigned int arr = atomicAdd(&g_barcnt, 1u);
        if (arr == (unsigned)gridDim.x - 1u) {
            g_barcnt = 0u;
            __threadfence();
            g_bargen = gen + 1u;
        } else {
            while (g_bargen <= gen) __nanosleep(32);
        }
        __threadfence();
    }
    __syncthreads();
    gen++;
}

__device__ __forceinline__ float4 suffix_shfl(float4 v, int lane) {
    #pragma unroll
    for (int o = 1; o < 32; o <<= 1) {
        float ux = __shfl_down_sync(0xffffffffu, v.x, o);
        float uy = __shfl_down_sync(0xffffffffu, v.y, o);
        float uz = __shfl_down_sync(0xffffffffu, v.z, o);
        float uw = __shfl_down_sync(0xffffffffu, v.w, o);
        if (lane + o < 32) { v.x += ux; v.y += uy; v.z += uz; v.w += uw; }
    }
    return v;
}

// ---------------------------------------------------------------------------
__global__ __launch_bounds__(256, 2) void k_fused(const float* __restrict__ x,
                                                  const float* __restrict__ w,
                                                  float* __restrict__ out) {
    int b = blockIdx.x;     // 0..255
    int tid = threadIdx.x;  // 0..255
    int lane = tid & 31, wq = tid >> 5;
    unsigned int gen = g_bargen;

    __shared__ float sbuf[KDIM];              // Phase0: w1|w2 (2048 floats); Phase1: s2 copy
    __shared__ int   ssig[CH];
    __shared__ float scb[CH], scd[CH];
    __shared__ float4 wtB[8], wtD[8];
    __shared__ float wtot[8], wsuf[8];
    __shared__ int   sT[16];
    __shared__ float sAZ[16], sCZ[16];

    // ===== Phase 0: scores + exp factors. Warp = 2 rows, 16 lanes/row. =====
    {
        // stage w1,w2 into smem (2048 floats)
        for (int j = tid; j < 2 * NDIM; j += 256) sbuf[j] = __ldg(w + j);
        __syncthreads();
        const float4* w1s = reinterpret_cast<const float4*>(sbuf);
        const float4* w2s = reinterpret_cast<const float4*>(sbuf + NDIM);

        int half = lane >> 4;            // 0 -> row A, 1 -> row B
        int jj = lane & 15;
        int row = b * 16 + 2 * wq + half;
        const float4* xr = reinterpret_cast<const float4*>(x + (size_t)row * NDIM);

        float4 xv[16];
        #pragma unroll
        for (int q = 0; q < 16; q++)
            xv[q] = __ldg(xr + q * 16 + jj);   // coalesced: 16 lanes contiguous

        float d1a = 0.f, d1b = 0.f, d2a = 0.f, d2b = 0.f;
        #pragma unroll
        for (int q = 0; q < 16; q++) {
            float4 a = w1s[q * 16 + jj];
            float4 c4 = w2s[q * 16 + jj];
            if (q & 1) {
                d1b += xv[q].x * a.x + xv[q].y * a.y + xv[q].z * a.z + xv[q].w * a.w;
                d2b += xv[q].x * c4.x + xv[q].y * c4.y + xv[q].z * c4.z + xv[q].w * c4.w;
            } else {
                d1a += xv[q].x * a.x + xv[q].y * a.y + xv[q].z * a.z + xv[q].w * a.w;
                d2a += xv[q].x * c4.x + xv[q].y * c4.y + xv[q].z * c4.z + xv[q].w * c4.w;
            }
        }
        float d1 = d1a + d1b, d2 = d2a + d2b;
        #pragma unroll
        for (int o = 8; o > 0; o >>= 1) {
            d1 += __shfl_down_sync(0xffffffffu, d1, o);
            d2 += __shfl_down_sync(0xffffffffu, d2, o);
        }
        if (jj == 0) {   // lanes 0 and 16 hold row A / row B sums
            g_s1[row] = d1;
            g_s2[row] = d2;
            g_ea[row] = __expf(d1);
            g_ec[row] = __expf(ALPHA * d1);
            g_eb[row] = __expf(d2);
            g_ed[row] = __expf(ALPHA * d2);
        }
    }
    gsync(gen);

    // ===== Phase 1: ranks. s2 staged in smem; warp = 2 rows. =====
    {
        for (int j = tid; j < KDIM; j += 256) sbuf[j] = g_s2[j];
        __syncthreads();
        int rA = b * 16 + 2 * wq;
        int rB = rA + 1;
        float vA = sbuf[rA], vB = sbuf[rB];
        int cA = 0, cB = 0;
        #pragma unroll 4
        for (int j = lane; j < KDIM; j += 32) {
            float u = sbuf[j];
            cA += (u < vA) || (u == vA && j < rA);
            cB += (u < vB) || (u == vB && j < rB);
        }
        #pragma unroll
        for (int o = 16; o > 0; o >>= 1) {
            cA += __shfl_down_sync(0xffffffffu, cA, o);
            cB += __shfl_down_sync(0xffffffffu, cB, o);
        }
        if (lane == 0) {
            g_sorted[cA] = vA; g_sigma[cA] = rA;
            g_ebS[cA] = g_eb[rA]; g_edS[cA] = g_ed[rA];
            g_sorted[cB] = vB; g_sigma[cB] = rB;
            g_ebS[cB] = g_eb[rB]; g_edS[cB] = g_ed[rB];
        }
    }
    gsync(gen);

    // ===== Phase 2: chunk-local vector suffix sums (block = chunk) =====
    {
        int c = b;
        int col = tid * 4;
        if (tid < CH) {
            int k = c * CH + tid;
            ssig[tid] = g_sigma[k];
            scb[tid] = g_ebS[k];
            scd[tid] = g_edS[k];
        }
        __syncthreads();
        float4 y[CH];
        #pragma unroll
        for (int r = 0; r < CH; r++)
            y[r] = __ldg(reinterpret_cast<const float4*>(x + (size_t)ssig[r] * NDIM + col));
        float4 aB = make_float4(0.f, 0.f, 0.f, 0.f);
        float4 aD = make_float4(0.f, 0.f, 0.f, 0.f);
        #pragma unroll
        for (int r = CH - 1; r >= 0; r--) {
            float cb = scb[r], cd = scd[r];
            aB.x = fmaf(cb, y[r].x, aB.x); aB.y = fmaf(cb, y[r].y, aB.y);
            aB.z = fmaf(cb, y[r].z, aB.z); aB.w = fmaf(cb, y[r].w, aB.w);
            aD.x = fmaf(cd, y[r].x, aD.x); aD.y = fmaf(cd, y[r].y, aD.y);
            aD.z = fmaf(cd, y[r].z, aD.z); aD.w = fmaf(cd, y[r].w, aD.w);
            size_t ro = (size_t)(c * CH + r) * NDIM + col;
            *reinterpret_cast<float4*>(g_sufB + ro) = aB;
            *reinterpret_cast<float4*>(g_sufD + ro) = aD;
        }
    }
    gsync(gen);

    // ===== Phase 3: carries (block = column quad, thread = chunk) =====
    {
        int col = b * 4;
        int c = tid;  // chunk
        size_t ro = (size_t)(c * CH) * NDIM + col;
        float4 tB = *reinterpret_cast<const float4*>(g_sufB + ro);  // chunk total
        float4 tD = *reinterpret_cast<const float4*>(g_sufD + ro);
        float4 iB = suffix_shfl(tB, lane);
        float4 iD = suffix_shfl(tD, lane);
        if (lane == 0) { wtB[wq] = iB; wtD[wq] = iD; }
        __syncthreads();
        float4 gB = make_float4(0.f, 0.f, 0.f, 0.f);
        float4 gD = make_float4(0.f, 0.f, 0.f, 0.f);
        #pragma unroll
        for (int g = 0; g < 8; g++) {
            if (g > wq) {
                float4 vB = wtB[g], vD = wtD[g];
                gB.x += vB.x; gB.y += vB.y; gB.z += vB.z; gB.w += vB.w;
                gD.x += vD.x; gD.y += vD.y; gD.z += vD.z; gD.w += vD.w;
            }
        }
        float4 eB = make_float4(iB.x - tB.x + gB.x, iB.y - tB.y + gB.y,
                                iB.z - tB.z + gB.z, iB.w - tB.w + gB.w);
        float4 eD = make_float4(iD.x - tD.x + gD.x, iD.y - tD.y + gD.y,
                                iD.z - tD.z + gD.z, iD.w - tD.w + gD.w);
        *reinterpret_cast<float4*>(g_carB + (size_t)c * NDIM + col) = eB;
        *reinterpret_cast<float4*>(g_carD + (size_t)c * NDIM + col) = eD;

        // block 0 additionally: scalar global suffix sums (16 elems/thread)
        if (b == 0) {
            __syncthreads();
            #pragma unroll
            for (int pass = 0; pass < 2; pass++) {
                const float* src = pass ? g_edS : g_ebS;
                float* dst = pass ? g_sd : g_sb;
                float e[16];
                float tot = 0.f;
                #pragma unroll
                for (int q = 0; q < 16; q++) { e[q] = src[16 * tid + q]; tot += e[q]; }
                float v = tot;
                #pragma unroll
                for (int o = 1; o < 32; o <<= 1) {
                    float u = __shfl_down_sync(0xffffffffu, v, o);
                    if (lane + o < 32) v += u;
                }
                if (lane == 0) wtot[wq] = v;
                __syncthreads();
                if (wq == 0 && lane < 8) {
                    float s = 0.f;
                    #pragma unroll
                    for (int q = 0; q < 8; q++) s += (q > lane) ? wtot[q] : 0.f;
                    wsuf[lane] = s;
                }
                __syncthreads();
                float s = (v - tot) + wsuf[wq];
                #pragma unroll
                for (int q = 15; q >= 0; q--) {
                    s += e[q];
                    dst[16 * tid + q] = s;
                }
                if (tid == 0) dst[KDIM] = 0.f;
                __syncthreads();
            }
        }
    }
    gsync(gen);

    // ===== Phase 4: outputs (16 rows per block, 4-row load batches) =====
    {
        int col = tid * 4;
        float4 sD0 = *reinterpret_cast<const float4*>(g_sufD + col);
        float4 cD0 = *reinterpret_cast<const float4*>(g_carD + col);
        float4 tD = make_float4(sD0.x + cD0.x, sD0.y + cD0.y,
                                sD0.z + cD0.z, sD0.w + cD0.w);
        if (tid < 16) {
            int i = b * 16 + tid;
            float key = -g_s1[i];
            int lo = 0, hi = KDIM;
            while (lo < hi) {
                int mid = (lo + hi) >> 1;
                if (g_sorted[mid] <= key) lo = mid + 1;
                else hi = mid;
            }
            int t = lo;
            float a = g_ea[i], c = g_ec[i];
            float Z = a * g_sb[t] + c * (g_sd[0] - g_sd[t]);
            float rZ = 1.f / Z;
            sT[tid] = t;
            sAZ[tid] = a * rZ;
            sCZ[tid] = c * rZ;
        }
        __syncthreads();
        #pragma unroll
        for (int g = 0; g < 16; g += 4) {
            float4 sB[4], cB[4], sD[4], cD[4];
            #pragma unroll
            for (int q = 0; q < 4; q++) {
                int t = sT[g + q];
                int tt = (t < KDIM) ? t : 0;
                int ch = tt / CH;
                size_t ro = (size_t)tt * NDIM + col;
                size_t co = (size_t)ch * NDIM + col;
                sB[q] = *reinterpret_cast<const float4*>(g_sufB + ro);
                cB[q] = *reinterpret_cast<const float4*>(g_carB + co);
                sD[q] = *reinterpret_cast<const float4*>(g_sufD + ro);
                cD[q] = *reinterpret_cast<const float4*>(g_carD + co);
            }
            #pragma unroll
            for (int q = 0; q < 4; q++) {
                int r = g + q;
                float aZ = sAZ[r], cZ = sCZ[r];
                float m = (sT[r] < KDIM) ? 1.f : 0.f;
                float4 h;
                h.x = aZ * m * (sB[q].x + cB[q].x) + cZ * (tD.x - m * (sD[q].x + cD[q].x));
                h.y = aZ * m * (sB[q].y + cB[q].y) + cZ * (tD.y - m * (sD[q].y + cD[q].y));
                h.z = aZ * m * (sB[q].z + cB[q].z) + cZ * (tD.z - m * (sD[q].z + cD[q].z));
                h.w = aZ * m * (sB[q].w + cB[q].w) + cZ * (tD.w - m * (sD[q].w + cD[q].w));
                *reinterpret_cast<float4*>(out + (size_t)(b * 16 + r) * NDIM + col) = h;
            }
        }
    }
}

// ---------------------------------------------------------------------------
extern "C" void kernel_launch(void* const* d_in, const int* in_sizes, int n_in,
                              void* d_out, int out_size) {
    const float* x = (const float*)d_in[0];   // (4096, 1024) fp32
    const float* w = (const float*)d_in[1];   // (2048, 1) fp32
    float* out = (float*)d_out;               // (4096, 1024) fp32

    k_fused<<<NBLK, 256>>>(x, w, out);
}

// round 12
// speedup vs baseline: 1.1822x; 1.1822x over previous
#include <cuda_runtime.h>
#include <cuda_bf16.h>
#include <cstdint>

#define ALPHA 0.2f
#define KDIM 4096
#define NDIM 1024
#define CH 16
#define NCHUNK (KDIM / CH)   // 256

// ---------------- scratch (__device__ globals; no allocs allowed) ----------
__device__ float g_s1[KDIM], g_s2[KDIM];
__device__ float g_ea[KDIM], g_ec[KDIM];        // exp(s1), exp(0.2 s1)
__device__ float g_eb[KDIM], g_ed[KDIM];        // exp(s2), exp(0.2 s2)
__device__ float g_sorted[KDIM];                // s2 ascending
__device__ int   g_sigma[KDIM];                 // sorted rank -> original index
__device__ float g_ebS[KDIM], g_edS[KDIM];      // eb/ed in sorted order
__device__ float g_sb[KDIM + 1], g_sd[KDIM + 1];// scalar global suffix sums
__device__ float g_sufB[(size_t)KDIM * NDIM];   // chunk-local vector suffix sums
__device__ float g_sufD[(size_t)KDIM * NDIM];
__device__ float g_carB[NCHUNK * NDIM];         // exclusive chunk-suffix carries
__device__ float g_carD[NCHUNK * NDIM];

__device__ __forceinline__ float4 suffix_shfl(float4 v, int lane) {
    #pragma unroll
    for (int o = 1; o < 32; o <<= 1) {
        float ux = __shfl_down_sync(0xffffffffu, v.x, o);
        float uy = __shfl_down_sync(0xffffffffu, v.y, o);
        float uz = __shfl_down_sync(0xffffffffu, v.z, o);
        float uw = __shfl_down_sync(0xffffffffu, v.w, o);
        if (lane + o < 32) { v.x += ux; v.y += uy; v.z += uz; v.w += uw; }
    }
    return v;
}

// ---------------------------------------------------------------------------
// K1: s1/s2 GEMV + exp factors. 1024 blocks x 4 rows, loads batched for MLP.
// ---------------------------------------------------------------------------
__global__ __launch_bounds__(256) void k_scores(const float* __restrict__ x,
                                                const float* __restrict__ w) {
    int b = blockIdx.x;           // 1024
    int t = threadIdx.x;          // 256 threads * float4 = 1024 cols
    int i0 = b * 4;
    const float4* w1 = reinterpret_cast<const float4*>(w);
    const float4* w2 = reinterpret_cast<const float4*>(w + NDIM);
    float4 a = __ldg(w1 + t);
    float4 bb = __ldg(w2 + t);
    float4 xv[4];
    #pragma unroll
    for (int r = 0; r < 4; r++)
        xv[r] = __ldg(reinterpret_cast<const float4*>(x + (size_t)(i0 + r) * NDIM) + t);

    __shared__ float sm1[4][8], sm2[4][8];
    #pragma unroll
    for (int r = 0; r < 4; r++) {
        float d1 = xv[r].x * a.x + xv[r].y * a.y + xv[r].z * a.z + xv[r].w * a.w;
        float d2 = xv[r].x * bb.x + xv[r].y * bb.y + xv[r].z * bb.z + xv[r].w * bb.w;
        #pragma unroll
        for (int o = 16; o > 0; o >>= 1) {
            d1 += __shfl_down_sync(0xffffffffu, d1, o);
            d2 += __shfl_down_sync(0xffffffffu, d2, o);
        }
        if ((t & 31) == 0) { sm1[r][t >> 5] = d1; sm2[r][t >> 5] = d2; }
    }
    __syncthreads();
    if (t < 4) {
        float s1 = 0.f, s2 = 0.f;
        #pragma unroll
        for (int q = 0; q < 8; q++) { s1 += sm1[t][q]; s2 += sm2[t][q]; }
        int i = i0 + t;
        g_s1[i] = s1;
        g_s2[i] = s2;
        g_ea[i] = __expf(s1);
        g_ec[i] = __expf(ALPHA * s1);
        g_eb[i] = __expf(s2);
        g_ed[i] = __expf(ALPHA * s2);
    }
}

// ---------------------------------------------------------------------------
// K2: ranks, 16 rows per block (256 blocks, ~4MB L2 traffic)
// ---------------------------------------------------------------------------
__global__ __launch_bounds__(256) void k_rank16() {
    int b = blockIdx.x;         // 256 blocks
    int tid = threadIdx.x;
    int i0 = b * 16;
    __shared__ float sv[16];
    __shared__ int scnt[16];
    if (tid < 16) { sv[tid] = g_s2[i0 + tid]; scnt[tid] = 0; }
    __syncthreads();
    int cnt[16];
    #pragma unroll
    for (int q = 0; q < 16; q++) cnt[q] = 0;
    for (int j = tid; j < KDIM; j += 256) {
        float u = g_s2[j];
        #pragma unroll
        for (int q = 0; q < 16; q++) {
            float v = sv[q];
            cnt[q] += (u < v) || (u == v && j < i0 + q);
        }
    }
    #pragma unroll
    for (int q = 0; q < 16; q++) {
        int r = cnt[q];
        #pragma unroll
        for (int o = 16; o > 0; o >>= 1) r += __shfl_down_sync(0xffffffffu, r, o);
        if ((tid & 31) == 0) atomicAdd(&scnt[q], r);
    }
    __syncthreads();
    if (tid < 16) {
        int r = scnt[tid];
        int i = i0 + tid;
        g_sorted[r] = sv[tid];
        g_sigma[r] = i;
        g_ebS[r] = g_eb[i];
        g_edS[r] = g_ed[i];
    }
}

// ---------------------------------------------------------------------------
// K3: chunk-local vector suffix sums. Block = chunk of CH=16 sorted rows,
// all 16 gathered rows loaded up-front into registers (MLP=16).
// ---------------------------------------------------------------------------
__global__ __launch_bounds__(256, 2) void k_scan(const float* __restrict__ x) {
    int c = blockIdx.x;
    int tid = threadIdx.x;
    int col = tid * 4;
    __shared__ int ssig[CH];
    __shared__ float scb[CH], scd[CH];
    if (tid < CH) {
        int k = c * CH + tid;
        ssig[tid] = g_sigma[k];
        scb[tid] = g_ebS[k];
        scd[tid] = g_edS[k];
    }
    __syncthreads();

    float4 y[CH];
    #pragma unroll
    for (int r = 0; r < CH; r++)
        y[r] = __ldg(reinterpret_cast<const float4*>(x + (size_t)ssig[r] * NDIM + col));

    float4 aB = make_float4(0.f, 0.f, 0.f, 0.f);
    float4 aD = make_float4(0.f, 0.f, 0.f, 0.f);

    #pragma unroll
    for (int r = CH - 1; r >= 0; r--) {
        float cb = scb[r], cd = scd[r];
        aB.x = fmaf(cb, y[r].x, aB.x); aB.y = fmaf(cb, y[r].y, aB.y);
        aB.z = fmaf(cb, y[r].z, aB.z); aB.w = fmaf(cb, y[r].w, aB.w);
        aD.x = fmaf(cd, y[r].x, aD.x); aD.y = fmaf(cd, y[r].y, aD.y);
        aD.z = fmaf(cd, y[r].z, aD.z); aD.w = fmaf(cd, y[r].w, aD.w);
        size_t ro = (size_t)(c * CH + r) * NDIM + col;
        *reinterpret_cast<float4*>(g_sufB + ro) = aB;
        *reinterpret_cast<float4*>(g_sufD + ro) = aD;
    }
}

// ---------------------------------------------------------------------------
// K4: carries, fully parallel. Blocks 0-255: block = column quad (col=b*4),
// thread = chunk; warp shfl suffix + smem cross-warp combine. Block 256:
// scalar global suffix sums of ebS/edS.
// ---------------------------------------------------------------------------
__global__ __launch_bounds__(256) void k_carry() {
    int tid = threadIdx.x;
    int lane = tid & 31, wq = tid >> 5;
    if (blockIdx.x < 256) {
        int col = blockIdx.x * 4;
        int c = tid;  // chunk
        __shared__ float4 wtB[8], wtD[8];
        size_t ro = (size_t)(c * CH) * NDIM + col;
        float4 tB = *reinterpret_cast<const float4*>(g_sufB + ro);  // chunk total
        float4 tD = *reinterpret_cast<const float4*>(g_sufD + ro);
        float4 iB = suffix_shfl(tB, lane);  // inclusive suffix within warp
        float4 iD = suffix_shfl(tD, lane);
        if (lane == 0) { wtB[wq] = iB; wtD[wq] = iD; }
        __syncthreads();
        float4 gB = make_float4(0.f, 0.f, 0.f, 0.f);
        float4 gD = make_float4(0.f, 0.f, 0.f, 0.f);
        #pragma unroll
        for (int g = 0; g < 8; g++) {
            if (g > wq) {
                float4 vB = wtB[g], vD = wtD[g];
                gB.x += vB.x; gB.y += vB.y; gB.z += vB.z; gB.w += vB.w;
                gD.x += vD.x; gD.y += vD.y; gD.z += vD.z; gD.w += vD.w;
            }
        }
        float4 eB = make_float4(iB.x - tB.x + gB.x, iB.y - tB.y + gB.y,
                                iB.z - tB.z + gB.z, iB.w - tB.w + gB.w);
        float4 eD = make_float4(iD.x - tD.x + gD.x, iD.y - tD.y + gD.y,
                                iD.z - tD.z + gD.z, iD.w - tD.w + gD.w);
        *reinterpret_cast<float4*>(g_carB + (size_t)c * NDIM + col) = eB;
        *reinterpret_cast<float4*>(g_carD + (size_t)c * NDIM + col) = eD;
    } else {
        // scalar suffix scans: thread t owns elems [16t, 16t+16)
        __shared__ float wtot[8], wsuf[8];
        #pragma unroll
        for (int pass = 0; pass < 2; pass++) {
            const float* src = pass ? g_edS : g_ebS;
            float* dst = pass ? g_sd : g_sb;
            float e[16];
            float tot = 0.f;
            #pragma unroll
            for (int q = 0; q < 16; q++) { e[q] = src[16 * tid + q]; tot += e[q]; }
            float v = tot;
            #pragma unroll
            for (int o = 1; o < 32; o <<= 1) {
                float u = __shfl_down_sync(0xffffffffu, v, o);
                if (lane + o < 32) v += u;
            }
            if (lane == 0) wtot[wq] = v;
            __syncthreads();
            if (wq == 0 && lane < 8) {
                float s = 0.f;
                #pragma unroll
                for (int q = 0; q < 8; q++) s += (q > lane) ? wtot[q] : 0.f;
                wsuf[lane] = s;
            }
            __syncthreads();
            float s = (v - tot) + wsuf[wq];
            #pragma unroll
            for (int q = 15; q >= 0; q--) {
                s += e[q];
                dst[16 * tid + q] = s;
            }
            if (tid == 0) dst[KDIM] = 0.f;
            __syncthreads();
        }
    }
}

// ---------------------------------------------------------------------------
// K5: outputs, 16 rows per block (256 blocks). TotD loaded once per block;
// suffix-table loads batched 4 rows deep.
// ---------------------------------------------------------------------------
__global__ __launch_bounds__(256) void k_out(float* __restrict__ out) {
    int b = blockIdx.x;
    int tid = threadIdx.x;
    int col = tid * 4;
    __shared__ int sT[16];
    __shared__ float sAZ[16], sCZ[16];

    float4 sD0 = *reinterpret_cast<const float4*>(g_sufD + col);
    float4 cD0 = *reinterpret_cast<const float4*>(g_carD + col);
    float4 tD = make_float4(sD0.x + cD0.x, sD0.y + cD0.y,
                            sD0.z + cD0.z, sD0.w + cD0.w);
    if (tid < 16) {
        int i = b * 16 + tid;
        float key = -g_s1[i];
        int lo = 0, hi = KDIM;
        while (lo < hi) {
            int mid = (lo + hi) >> 1;
            if (g_sorted[mid] <= key) lo = mid + 1;
            else hi = mid;
        }
        int t = lo;
        float a = g_ea[i], c = g_ec[i];
        float Z = a * g_sb[t] + c * (g_sd[0] - g_sd[t]);
        float rZ = 1.f / Z;
        sT[tid] = t;
        sAZ[tid] = a * rZ;
        sCZ[tid] = c * rZ;
    }
    __syncthreads();
    #pragma unroll
    for (int g = 0; g < 16; g += 4) {
        float4 sB[4], cB[4], sD[4], cD[4];
        #pragma unroll
        for (int q = 0; q < 4; q++) {
            int t = sT[g + q];
            int tt = (t < KDIM) ? t : 0;
            int ch = tt / CH;
            size_t ro = (size_t)tt * NDIM + col;
            size_t co = (size_t)ch * NDIM + col;
            sB[q] = *reinterpret_cast<const float4*>(g_sufB + ro);
            cB[q] = *reinterpret_cast<const float4*>(g_carB + co);
            sD[q] = *reinterpret_cast<const float4*>(g_sufD + ro);
            cD[q] = *reinterpret_cast<const float4*>(g_carD + co);
        }
        #pragma unroll
        for (int q = 0; q < 4; q++) {
            int r = g + q;
            float aZ = sAZ[r], cZ = sCZ[r];
            float m = (sT[r] < KDIM) ? 1.f : 0.f;
            float4 h;
            h.x = aZ * m * (sB[q].x + cB[q].x) + cZ * (tD.x - m * (sD[q].x + cD[q].x));
            h.y = aZ * m * (sB[q].y + cB[q].y) + cZ * (tD.y - m * (sD[q].y + cD[q].y));
            h.z = aZ * m * (sB[q].z + cB[q].z) + cZ * (tD.z - m * (sD[q].z + cD[q].z));
            h.w = aZ * m * (sB[q].w + cB[q].w) + cZ * (tD.w - m * (sD[q].w + cD[q].w));
            *reinterpret_cast<float4*>(out + (size_t)(b * 16 + r) * NDIM + col) = h;
        }
    }
}

// ---------------------------------------------------------------------------
extern "C" void kernel_launch(void* const* d_in, const int* in_sizes, int n_in,
                              void* d_out, int out_size) {
    const float* x = (const float*)d_in[0];   // (4096, 1024) fp32
    const float* w = (const float*)d_in[1];   // (2048, 1) fp32
    float* out = (float*)d_out;               // (4096, 1024) fp32

    k_scores<<<KDIM / 4, 256>>>(x, w);
    k_rank16<<<NCHUNK, 256>>>();
    k_scan<<<NCHUNK, 256>>>(x);
    k_carry<<<257, 256>>>();
    k_out<<<NCHUNK, 256>>>(out);
}